// round 1
// baseline (speedup 1.0000x reference)
#include <cuda_runtime.h>

// Problem constants (fixed by the dataset):
//   NU = NI = 100000 nodes, E = 600000 edges per etype, DIN = DOUT = 128.
#define NNODE 100000
#define F 128
#define NE_MAX 600000
#define SCAN_BLK 1024
#define NSCAN 98            // ceil(100000 / 1024)

// ---------------------------------------------------------------------------
// Static device scratch (no allocations allowed in kernel_launch).
// ---------------------------------------------------------------------------
__device__ float g_Wh[3][(size_t)NNODE * F];   // projected src features per etype
__device__ int   g_rowptr[3][NNODE + 1];       // CSR row pointers (counts during hist)
__device__ int   g_fill[3][NNODE];             // per-dst fill cursors
__device__ int   g_col[3][NE_MAX];             // CSR column (src) indices
__device__ int   g_part[3][128];               // scan block partials

// ---------------------------------------------------------------------------
// Packed f32x2 helpers (Blackwell: 2x fp32 FMA rate vs scalar FFMA)
// ---------------------------------------------------------------------------
__device__ __forceinline__ unsigned long long pack2(float x, float y) {
    unsigned long long r;
    asm("mov.b64 %0, {%1, %2};" : "=l"(r) : "f"(x), "f"(y));
    return r;
}
__device__ __forceinline__ void unpack2(unsigned long long v, float& x, float& y) {
    asm("mov.b64 {%0, %1}, %2;" : "=f"(x), "=f"(y) : "l"(v));
}
__device__ __forceinline__ unsigned long long ffma2(unsigned long long a,
                                                    unsigned long long b,
                                                    unsigned long long c) {
    unsigned long long d;
    asm("fma.rn.f32x2 %0, %1, %2, %3;" : "=l"(d) : "l"(a), "l"(b), "l"(c));
    return d;
}

// ---------------------------------------------------------------------------
// GEMM: Wh[etype] = A(Mx128) @ W(128x128) + bias.  BM=128, BN=128, BK=32.
// 256 threads, 8x8 microtile per thread, packed f32x2 FMAs.
// ---------------------------------------------------------------------------
#define BM 128
#define BN 128
#define BK 32

__global__ void __launch_bounds__(256, 2) gemm_bias_kernel(
    const float* __restrict__ A, const float* __restrict__ W,
    const float* __restrict__ bias, int etype, int M)
{
    __shared__ float As[BM][BK + 4];   // +4 pad: conflict-free, keeps 16B align
    __shared__ float Bs[BK][BN];

    float* C = g_Wh[etype];
    const int bm  = blockIdx.x * BM;
    const int tid = threadIdx.x;
    const int ty  = tid >> 4;          // 0..15 -> rows ty*8..ty*8+7
    const int tx  = tid & 15;          // 0..15 -> cols tx*8..tx*8+7

    unsigned long long acc[8][4];
    #pragma unroll
    for (int i = 0; i < 8; i++)
        #pragma unroll
        for (int p = 0; p < 4; p++) acc[i][p] = 0ull;

    for (int k0 = 0; k0 < F; k0 += BK) {
        // Load A tile: 128 rows x 32 cols (8 float4 per row)
        #pragma unroll
        for (int t = tid; t < BM * BK / 4; t += 256) {
            int r  = t >> 3;
            int c4 = t & 7;
            int row = bm + r;
            float4 v = make_float4(0.f, 0.f, 0.f, 0.f);
            if (row < M)
                v = *(const float4*)(A + (size_t)row * F + k0 + c4 * 4);
            As[r][c4 * 4 + 0] = v.x;
            As[r][c4 * 4 + 1] = v.y;
            As[r][c4 * 4 + 2] = v.z;
            As[r][c4 * 4 + 3] = v.w;
        }
        // Load B tile: 32 rows x 128 cols
        #pragma unroll
        for (int t = tid; t < BK * BN / 4; t += 256) {
            int r  = t >> 5;
            int c4 = t & 31;
            *(float4*)(&Bs[r][c4 * 4]) =
                *(const float4*)(W + (size_t)(k0 + r) * F + c4 * 4);
        }
        __syncthreads();

        #pragma unroll 8
        for (int k = 0; k < BK; k++) {
            float a[8];
            #pragma unroll
            for (int i = 0; i < 8; i++) a[i] = As[ty * 8 + i][k];
            float4 b0 = *(const float4*)(&Bs[k][tx * 8]);
            float4 b1 = *(const float4*)(&Bs[k][tx * 8 + 4]);
            unsigned long long bp[4];
            bp[0] = pack2(b0.x, b0.y);
            bp[1] = pack2(b0.z, b0.w);
            bp[2] = pack2(b1.x, b1.y);
            bp[3] = pack2(b1.z, b1.w);
            #pragma unroll
            for (int i = 0; i < 8; i++) {
                unsigned long long ap = pack2(a[i], a[i]);
                #pragma unroll
                for (int p = 0; p < 4; p++)
                    acc[i][p] = ffma2(ap, bp[p], acc[i][p]);
            }
        }
        __syncthreads();
    }

    // Epilogue: unpack, add bias, store
    float bj[8];
    #pragma unroll
    for (int j = 0; j < 8; j++) bj[j] = bias[tx * 8 + j];

    #pragma unroll
    for (int i = 0; i < 8; i++) {
        int row = bm + ty * 8 + i;
        if (row < M) {
            float o[8];
            #pragma unroll
            for (int p = 0; p < 4; p++)
                unpack2(acc[i][p], o[2 * p], o[2 * p + 1]);
            float4 v0 = make_float4(o[0] + bj[0], o[1] + bj[1], o[2] + bj[2], o[3] + bj[3]);
            float4 v1 = make_float4(o[4] + bj[4], o[5] + bj[5], o[6] + bj[6], o[7] + bj[7]);
            *(float4*)(C + (size_t)row * F + tx * 8)     = v0;
            *(float4*)(C + (size_t)row * F + tx * 8 + 4) = v1;
        }
    }
}

// ---------------------------------------------------------------------------
// CSR build: zero -> histogram -> 3-phase exclusive scan -> fill
// ---------------------------------------------------------------------------
__global__ void zero_kernel() {
    int i = blockIdx.x * blockDim.x + threadIdx.x;
    if (i < 3 * (NNODE + 1)) ((int*)g_rowptr)[i] = 0;
    if (i < 3 * NNODE)       ((int*)g_fill)[i]   = 0;
}

__global__ void hist_kernel(const int* __restrict__ d0, const int* __restrict__ d1,
                            const int* __restrict__ d2, int e0, int e1, int e2) {
    int e = blockIdx.y;
    const int* d = (e == 0) ? d0 : (e == 1) ? d1 : d2;
    int n = (e == 0) ? e0 : (e == 1) ? e1 : e2;
    int i = blockIdx.x * blockDim.x + threadIdx.x;
    if (i < n) atomicAdd(&g_rowptr[e][d[i]], 1);
}

__global__ void scan_blocks_kernel() {
    int e = blockIdx.y;
    int i = blockIdx.x * SCAN_BLK + threadIdx.x;
    int val = (i < NNODE) ? g_rowptr[e][i] : 0;

    int lane = threadIdx.x & 31, wid = threadIdx.x >> 5;
    int x = val;
    #pragma unroll
    for (int o = 1; o < 32; o <<= 1) {
        int y = __shfl_up_sync(0xffffffffu, x, o);
        if (lane >= o) x += y;
    }
    __shared__ int ws[32];
    if (lane == 31) ws[wid] = x;
    __syncthreads();
    if (wid == 0) {
        int v = ws[lane];
        #pragma unroll
        for (int o = 1; o < 32; o <<= 1) {
            int y = __shfl_up_sync(0xffffffffu, v, o);
            if (lane >= o) v += y;
        }
        ws[lane] = v;   // inclusive over warp sums
    }
    __syncthreads();
    int off = wid ? ws[wid - 1] : 0;
    int excl = x - val + off;
    if (i < NNODE) g_rowptr[e][i] = excl;
    if (threadIdx.x == SCAN_BLK - 1) g_part[e][blockIdx.x] = x + off;  // block total
}

__global__ void scan_parts_kernel(int n) {
    int e = blockIdx.x, t = threadIdx.x;     // 128 threads, n <= 128
    int val = (t < n) ? g_part[e][t] : 0;
    int lane = t & 31, wid = t >> 5;
    int x = val;
    #pragma unroll
    for (int o = 1; o < 32; o <<= 1) {
        int y = __shfl_up_sync(0xffffffffu, x, o);
        if (lane >= o) x += y;
    }
    __shared__ int ws[4];
    if (lane == 31) ws[wid] = x;
    __syncthreads();
    if (t == 0) {
        int s = 0;
        for (int w = 0; w < 4; w++) { int v = ws[w]; ws[w] = s; s += v; }
    }
    __syncthreads();
    int excl = x - val + ws[wid];
    if (t < n) g_part[e][t] = excl;
}

__global__ void scan_add_kernel(int e0, int e1, int e2) {
    int e = blockIdx.y;
    int i = blockIdx.x * SCAN_BLK + threadIdx.x;
    if (i < NNODE) g_rowptr[e][i] += g_part[e][blockIdx.x];
    if (blockIdx.x == 0 && threadIdx.x == 0) {
        int ne = (e == 0) ? e0 : (e == 1) ? e1 : e2;
        g_rowptr[e][NNODE] = ne;
    }
}

__global__ void fill_kernel(const int* __restrict__ s0, const int* __restrict__ d0,
                            const int* __restrict__ s1, const int* __restrict__ d1,
                            const int* __restrict__ s2, const int* __restrict__ d2,
                            int e0, int e1, int e2) {
    int e = blockIdx.y;
    const int* s = (e == 0) ? s0 : (e == 1) ? s1 : s2;
    const int* d = (e == 0) ? d0 : (e == 1) ? d1 : d2;
    int n = (e == 0) ? e0 : (e == 1) ? e1 : e2;
    int i = blockIdx.x * blockDim.x + threadIdx.x;
    if (i < n) {
        int dd = d[i];
        int p = g_rowptr[e][dd] + atomicAdd(&g_fill[e][dd], 1);
        g_col[e][p] = s[i];
    }
}

// ---------------------------------------------------------------------------
// Pull-mean: one warp per dst node, each lane owns one float4 of the 128-dim row.
// ---------------------------------------------------------------------------
__global__ void pull_item_kernel(float* __restrict__ out) {
    int w = (blockIdx.x * blockDim.x + threadIdx.x) >> 5;
    int lane = threadIdx.x & 31;
    if (w >= NNODE) return;
    int beg = g_rowptr[0][w], end = g_rowptr[0][w + 1];
    const float4* Wh = (const float4*)g_Wh[0];
    float4 acc = make_float4(0.f, 0.f, 0.f, 0.f);
    for (int j = beg; j < end; j++) {
        int c = g_col[0][j];
        float4 v = Wh[(size_t)c * 32 + lane];
        acc.x += v.x; acc.y += v.y; acc.z += v.z; acc.w += v.w;
    }
    float inv = (end > beg) ? 1.0f / (float)(end - beg) : 0.0f;
    acc.x *= inv; acc.y *= inv; acc.z *= inv; acc.w *= inv;
    ((float4*)out)[(size_t)w * 32 + lane] = acc;
}

__global__ void pull_user_kernel(float* __restrict__ out) {
    int w = (blockIdx.x * blockDim.x + threadIdx.x) >> 5;
    int lane = threadIdx.x & 31;
    if (w >= NNODE) return;

    // etype iu (item->user): g_Wh[1], csr 1
    int beg1 = g_rowptr[1][w], end1 = g_rowptr[1][w + 1];
    const float4* Wh1 = (const float4*)g_Wh[1];
    float4 a1 = make_float4(0.f, 0.f, 0.f, 0.f);
    for (int j = beg1; j < end1; j++) {
        int c = g_col[1][j];
        float4 v = Wh1[(size_t)c * 32 + lane];
        a1.x += v.x; a1.y += v.y; a1.z += v.z; a1.w += v.w;
    }
    float inv1 = (end1 > beg1) ? 1.0f / (float)(end1 - beg1) : 0.0f;

    // etype uu (user->user): g_Wh[2], csr 2
    int beg2 = g_rowptr[2][w], end2 = g_rowptr[2][w + 1];
    const float4* Wh2 = (const float4*)g_Wh[2];
    float4 a2 = make_float4(0.f, 0.f, 0.f, 0.f);
    for (int j = beg2; j < end2; j++) {
        int c = g_col[2][j];
        float4 v = Wh2[(size_t)c * 32 + lane];
        a2.x += v.x; a2.y += v.y; a2.z += v.z; a2.w += v.w;
    }
    float inv2 = (end2 > beg2) ? 1.0f / (float)(end2 - beg2) : 0.0f;

    float4 r;
    r.x = a1.x * inv1 + a2.x * inv2;
    r.y = a1.y * inv1 + a2.y * inv2;
    r.z = a1.z * inv1 + a2.z * inv2;
    r.w = a1.w * inv1 + a2.w * inv2;
    ((float4*)out)[(size_t)w * 32 + lane] = r;
}

// ---------------------------------------------------------------------------
// kernel_launch
// ---------------------------------------------------------------------------
extern "C" void kernel_launch(void* const* d_in, const int* in_sizes, int n_in,
                              void* d_out, int out_size) {
    const float* feat_user = (const float*)d_in[0];
    const float* feat_item = (const float*)d_in[1];
    const float* W_ui = (const float*)d_in[2];
    const float* b_ui = (const float*)d_in[3];
    const float* W_iu = (const float*)d_in[4];
    const float* b_iu = (const float*)d_in[5];
    const float* W_uu = (const float*)d_in[6];
    const float* b_uu = (const float*)d_in[7];
    const int* src_ui = (const int*)d_in[8];
    const int* dst_ui = (const int*)d_in[9];
    const int* src_iu = (const int*)d_in[10];
    const int* dst_iu = (const int*)d_in[11];
    const int* src_uu = (const int*)d_in[12];
    const int* dst_uu = (const int*)d_in[13];
    float* out = (float*)d_out;

    int E0 = in_sizes[8], E1 = in_sizes[10], E2 = in_sizes[12];
    int Emax = E0 > E1 ? (E0 > E2 ? E0 : E2) : (E1 > E2 ? E1 : E2);
    int eblocks = (Emax + 255) / 256;

    // CSR build
    zero_kernel<<<(3 * (NNODE + 1) + 255) / 256, 256>>>();
    hist_kernel<<<dim3(eblocks, 3), 256>>>(dst_ui, dst_iu, dst_uu, E0, E1, E2);
    scan_blocks_kernel<<<dim3(NSCAN, 3), SCAN_BLK>>>();
    scan_parts_kernel<<<3, 128>>>(NSCAN);
    scan_add_kernel<<<dim3(NSCAN, 3), SCAN_BLK>>>(E0, E1, E2);
    fill_kernel<<<dim3(eblocks, 3), 256>>>(src_ui, dst_ui, src_iu, dst_iu,
                                           src_uu, dst_uu, E0, E1, E2);

    // Projections: Wh[e] = feat @ W_e + b_e
    int gblocks = (NNODE + BM - 1) / BM;
    gemm_bias_kernel<<<gblocks, 256>>>(feat_user, W_ui, b_ui, 0, NNODE);
    gemm_bias_kernel<<<gblocks, 256>>>(feat_item, W_iu, b_iu, 1, NNODE);
    gemm_bias_kernel<<<gblocks, 256>>>(feat_user, W_uu, b_uu, 2, NNODE);

    // Pull-mean aggregation: out[1] = h_item, out[0] = h_user
    int pblocks = (NNODE * 32 + 255) / 256;
    pull_item_kernel<<<pblocks, 256>>>(out + (size_t)NNODE * F);
    pull_user_kernel<<<pblocks, 256>>>(out);
}